// round 1
// baseline (speedup 1.0000x reference)
#include <cuda_runtime.h>
#include <math.h>

// ---------------- problem constants ----------------
#define B_      8
#define H_      128
#define W_      128
#define DIM_    256
#define HEADS_  16
#define DH_     16
#define HW_     (H_*W_)            // 16384
#define M_TOTAL (B_*HW_)           // 131072
#define N_QKV   (3*DIM_)           // 768

// ---------------- scratch (no allocs allowed -> __device__ globals) ----------------
__device__ float g_qkv [(size_t)M_TOTAL * N_QKV];   // pre-conv qkv   (~403 MB)
__device__ float g_qkv2[(size_t)M_TOTAL * N_QKV];   // post-conv qkv  (~403 MB)
__device__ float g_attn[B_ * HEADS_ * DH_ * DH_];   // softmaxed attention
__device__ float g_wf  [B_ * DIM_ * DIM_];          // fused blockdiag(attn) @ w_out

// ---------------- f32x2 helpers (FFMA2 path, 2x fp32 rate) ----------------
#define PACK2(d, lo, hi)  asm("mov.b64 %0, {%1, %2};" : "=l"(d) : "f"(lo), "f"(hi))
#define UNPACK2(lo, hi, s) asm("mov.b64 {%0, %1}, %2;" : "=f"(lo), "=f"(hi) : "l"(s))
#define FMA2(d, a, b)     asm("fma.rn.f32x2 %0, %1, %2, %0;" : "+l"(d) : "l"(a), "l"(b))

// ---------------- GEMM: C[M,N] = A[M,K] @ B[K,N], fp32, f32x2 inner loop -------------
// Supports per-batch B matrices: batch = m0 / rows_per_batch, Bp = B + batch*b_stride.
#define BM  128
#define BN  64
#define BKK 16

__global__ __launch_bounds__(256) void gemm_k(
    const float* __restrict__ A, int lda,
    const float* __restrict__ Bm, int ldb, int b_stride,
    float* __restrict__ C, int ldc,
    int rows_per_batch, int K)
{
    __shared__ __align__(16) float As[BKK][BM];   // k-major: rows contiguous -> f32x2 pairs
    __shared__ __align__(16) float Bs[BKK][BN];

    const int tid = threadIdx.x;
    const int m0  = blockIdx.y * BM;
    const int n0  = blockIdx.x * BN;
    const int batch = m0 / rows_per_batch;
    const float* Ap = A  + (size_t)m0 * lda;
    const float* Bp = Bm + (size_t)batch * b_stride;

    const int ty = tid >> 4, tx = tid & 15;
    const int mrow = ty * 8;     // 8 rows per thread (4 row-pairs)
    const int ncol = tx * 4;     // 4 cols per thread

    unsigned long long acc[4][4];
    #pragma unroll
    for (int i = 0; i < 4; i++)
        #pragma unroll
        for (int j = 0; j < 4; j++) acc[i][j] = 0ull;   // (0.f,0.f)

    for (int kt = 0; kt < K; kt += BKK) {
        // load A tile (BM x BK), store transposed As[k][m]
        #pragma unroll
        for (int q = 0; q < 2; q++) {
            int idx = tid * 2 + q;          // 0..511
            int r   = idx >> 2;             // 0..127
            int kk  = (idx & 3) * 4;        // 0,4,8,12
            float4 v = *(const float4*)(Ap + (size_t)r * lda + kt + kk);
            As[kk+0][r] = v.x; As[kk+1][r] = v.y;
            As[kk+2][r] = v.z; As[kk+3][r] = v.w;
        }
        // load B tile (BK x BN)
        {
            int kk = tid >> 4;              // 0..15
            int nn = (tid & 15) * 4;        // 0..60
            *(float4*)&Bs[kk][nn] =
                *(const float4*)(Bp + (size_t)(kt + kk) * ldb + n0 + nn);
        }
        __syncthreads();

        #pragma unroll
        for (int k = 0; k < BKK; k++) {
            ulonglong2 aa0 = *(const ulonglong2*)&As[k][mrow];      // rows (0,1),(2,3)
            ulonglong2 aa1 = *(const ulonglong2*)&As[k][mrow + 4];  // rows (4,5),(6,7)
            float4 bv = *(const float4*)&Bs[k][ncol];
            unsigned long long b2[4];
            PACK2(b2[0], bv.x, bv.x);
            PACK2(b2[1], bv.y, bv.y);
            PACK2(b2[2], bv.z, bv.z);
            PACK2(b2[3], bv.w, bv.w);
            unsigned long long a2[4] = {aa0.x, aa0.y, aa1.x, aa1.y};
            #pragma unroll
            for (int rp = 0; rp < 4; rp++)
                #pragma unroll
                for (int j = 0; j < 4; j++)
                    FMA2(acc[rp][j], a2[rp], b2[j]);
        }
        __syncthreads();
    }

    #pragma unroll
    for (int rp = 0; rp < 4; rp++) {
        float lo[4], hi[4];
        #pragma unroll
        for (int j = 0; j < 4; j++) UNPACK2(lo[j], hi[j], acc[rp][j]);
        size_t row = (size_t)m0 + mrow + rp * 2;
        float4 v0 = make_float4(lo[0], lo[1], lo[2], lo[3]);
        float4 v1 = make_float4(hi[0], hi[1], hi[2], hi[3]);
        *(float4*)(C + row       * ldc + n0 + ncol) = v0;
        *(float4*)(C + (row + 1) * ldc + n0 + ncol) = v1;
    }
}

// ---------------- depthwise 3x3 conv, SAME padding, NHWC, fp32 ----------------
__global__ void dwconv_k(const float* __restrict__ in,
                         const float* __restrict__ w,
                         float* __restrict__ out)
{
    const int C4 = N_QKV / 4;   // 192
    int idx = blockIdx.x * blockDim.x + threadIdx.x;
    if (idx >= B_ * H_ * W_ * C4) return;
    int c4 = idx % C4;
    int t  = idx / C4;
    int xx = t % W_;  t /= W_;
    int yy = t % H_;
    int b  = t / H_;

    float4 acc = make_float4(0.f, 0.f, 0.f, 0.f);
    #pragma unroll
    for (int dy = 0; dy < 3; dy++) {
        int y2 = yy + dy - 1;
        if ((unsigned)y2 >= (unsigned)H_) continue;
        #pragma unroll
        for (int dx = 0; dx < 3; dx++) {
            int x2 = xx + dx - 1;
            if ((unsigned)x2 >= (unsigned)W_) continue;
            float4 iv = *(const float4*)(in + ((size_t)(b*H_ + y2)*W_ + x2)*N_QKV + c4*4);
            float4 wv = *(const float4*)(w  + (size_t)(dy*3 + dx)*N_QKV + c4*4);
            acc.x += iv.x*wv.x; acc.y += iv.y*wv.y;
            acc.z += iv.z*wv.z; acc.w += iv.w*wv.w;
        }
    }
    *(float4*)(out + ((size_t)(b*H_ + yy)*W_ + xx)*N_QKV + c4*4) = acc;
}

// ---------------- channel attention: normalize q,k; attn = k^T q; softmax(axis=-2) ---
// one block per (b, head). 256 threads: 4 s-groups x (16 i x 4 j-quads)
__global__ __launch_bounds__(256) void attn_k(
    const float* __restrict__ qkv2,
    const float* __restrict__ mean_q, const float* __restrict__ var_q,
    const float* __restrict__ mean_k, const float* __restrict__ var_k,
    const float* __restrict__ temp,
    float* __restrict__ attn_out)
{
    const int bh = blockIdx.x;
    const int b = bh >> 4, h = bh & 15;
    __shared__ float qs[64][16];
    __shared__ float ks[64][16];
    __shared__ float red[4][16][16];
    __shared__ float sm[16][16];

    const int tid = threadIdx.x;
    const int g  = tid >> 6;          // s-group 0..3
    const int r  = tid & 63;
    const int i  = r >> 2;            // 0..15  (k channel)
    const int j4 = r & 3;             // 0..3   (q channel quad)
    const int ls = tid >> 2;          // load: s within chunk 0..63
    const int li = (tid & 3) * 4;     // load: channel 0,4,8,12
    const float* base = qkv2 + (size_t)b * HW_ * N_QKV + h * DH_;

    float acc0 = 0.f, acc1 = 0.f, acc2 = 0.f, acc3 = 0.f;

    for (int s0 = 0; s0 < HW_; s0 += 64) {
        int s = s0 + ls;
        float mq = mean_q[s], rvq = rsqrtf(var_q[s]);
        float mk = mean_k[s], rvk = rsqrtf(var_k[s]);
        const float* p = base + (size_t)s * N_QKV + li;
        float4 qv = *(const float4*)(p);
        float4 kv = *(const float4*)(p + DIM_);
        qs[ls][li+0] = (qv.x - mq) * rvq;
        qs[ls][li+1] = (qv.y - mq) * rvq;
        qs[ls][li+2] = (qv.z - mq) * rvq;
        qs[ls][li+3] = (qv.w - mq) * rvq;
        ks[ls][li+0] = (kv.x - mk) * rvk;
        ks[ls][li+1] = (kv.y - mk) * rvk;
        ks[ls][li+2] = (kv.z - mk) * rvk;
        ks[ls][li+3] = (kv.w - mk) * rvk;
        __syncthreads();

        #pragma unroll
        for (int t = 0; t < 16; t++) {
            int ss = g * 16 + t;
            float kval = ks[ss][i];
            acc0 += kval * qs[ss][j4*4+0];
            acc1 += kval * qs[ss][j4*4+1];
            acc2 += kval * qs[ss][j4*4+2];
            acc3 += kval * qs[ss][j4*4+3];
        }
        __syncthreads();
    }

    red[g][i][j4*4+0] = acc0;
    red[g][i][j4*4+1] = acc1;
    red[g][i][j4*4+2] = acc2;
    red[g][i][j4*4+3] = acc3;
    __syncthreads();

    const int i2 = tid >> 4;   // 0..15
    const int j2 = tid & 15;
    float a = red[0][i2][j2] + red[1][i2][j2] + red[2][i2][j2] + red[3][i2][j2];
    a *= temp[j2];             // temperature broadcasts over last axis (j)
    sm[i2][j2] = a;
    __syncthreads();

    if (tid < 16) {            // softmax over i (axis=-2), one thread per column j
        int j = tid;
        float mx = -1e30f;
        #pragma unroll
        for (int ii = 0; ii < 16; ii++) mx = fmaxf(mx, sm[ii][j]);
        float e[16]; float ssum = 0.f;
        #pragma unroll
        for (int ii = 0; ii < 16; ii++) { e[ii] = expf(sm[ii][j] - mx); ssum += e[ii]; }
        float inv = 1.f / ssum;
        #pragma unroll
        for (int ii = 0; ii < 16; ii++)
            attn_out[((size_t)bh * 16 + ii) * 16 + j] = e[ii] * inv;
    }
}

// ---------------- Wfused[b][h*16+d][e] = sum_j attn[b,h,d,j] * w_out[h*16+j][e] ------
__global__ __launch_bounds__(256) void wfused_k(const float* __restrict__ attn,
                                                const float* __restrict__ w_out,
                                                float* __restrict__ wf)
{
    const int bh = blockIdx.x;
    const int b = bh >> 4, h = bh & 15;
    const int e = threadIdx.x;    // 0..255 output channel
    __shared__ float a[16][16];
    a[threadIdx.x >> 4][threadIdx.x & 15] = attn[(size_t)bh * 256 + threadIdx.x];
    __syncthreads();

    float w[16];
    #pragma unroll
    for (int j = 0; j < 16; j++) w[j] = w_out[(size_t)(h*16 + j) * DIM_ + e];
    #pragma unroll
    for (int d = 0; d < 16; d++) {
        float s = 0.f;
        #pragma unroll
        for (int j = 0; j < 16; j++) s += a[d][j] * w[j];
        wf[((size_t)b * DIM_ + h*16 + d) * DIM_ + e] = s;
    }
}

// ---------------- launch ----------------
extern "C" void kernel_launch(void* const* d_in, const int* in_sizes, int n_in,
                              void* d_out, int out_size)
{
    const float* x      = (const float*)d_in[0];
    const float* w_qkv  = (const float*)d_in[1];
    const float* w_dw   = (const float*)d_in[2];
    const float* w_out  = (const float*)d_in[3];
    const float* temp   = (const float*)d_in[4];
    const float* mean_q = (const float*)d_in[5];
    const float* var_q  = (const float*)d_in[6];
    const float* mean_k = (const float*)d_in[7];
    const float* var_k  = (const float*)d_in[8];
    float* out = (float*)d_out;

    float *qkv, *qkv2, *attn, *wf;
    cudaGetSymbolAddress((void**)&qkv,  g_qkv);
    cudaGetSymbolAddress((void**)&qkv2, g_qkv2);
    cudaGetSymbolAddress((void**)&attn, g_attn);
    cudaGetSymbolAddress((void**)&wf,   g_wf);

    // 1) QKV projection: (131072 x 256) @ (256 x 768)
    gemm_k<<<dim3(N_QKV / BN, M_TOTAL / BM), 256>>>(
        x, DIM_, w_qkv, N_QKV, 0, qkv, N_QKV, M_TOTAL, DIM_);

    // 2) depthwise 3x3 conv, SAME
    {
        int total = B_ * H_ * W_ * (N_QKV / 4);
        dwconv_k<<<(total + 255) / 256, 256>>>(qkv, w_dw, qkv2);
    }

    // 3) per-(b,head) normalized channel attention + softmax
    attn_k<<<B_ * HEADS_, 256>>>(qkv2, mean_q, var_q, mean_k, var_k, temp, attn);

    // 4) fold attn into output projection: Wfused = blockdiag(attn) @ w_out
    wfused_k<<<B_ * HEADS_, 256>>>(attn, w_out, wf);

    // 5) out = v_flat @ Wfused[b]  (per-batch B matrix), (16384 x 256) @ (256 x 256) x 8
    gemm_k<<<dim3(DIM_ / BN, M_TOTAL / BM), 256>>>(
        qkv2 + 2 * DIM_, N_QKV, wf, DIM_, DIM_ * DIM_, out, DIM_, HW_, DIM_);
}

// round 3
// speedup vs baseline: 2.4411x; 2.4411x over previous
#include <cuda_runtime.h>
#include <math.h>
#include <stdint.h>

// ---------------- problem constants ----------------
#define B_      8
#define H_      128
#define W_      128
#define DIM_    256
#define HEADS_  16
#define DH_     16
#define HW_     (H_*W_)            // 16384
#define M_TOTAL (B_*HW_)           // 131072
#define N_QKV   (3*DIM_)           // 768
#define SLICES  8

// ---------------- scratch (no allocs -> __device__ globals) ----------------
__device__ float g_qkv  [(size_t)M_TOTAL * N_QKV];    // pre-conv qkv
__device__ float g_qkv2 [(size_t)M_TOTAL * N_QKV];    // post-conv qkv
__device__ float g_part [SLICES * B_ * HEADS_ * DH_ * DH_];
__device__ float g_attn [B_ * HEADS_ * DH_ * DH_];
__device__ float g_wfT  [B_ * DIM_ * DIM_];           // (blockdiag(attn)@w_out)^T per batch: [e][k]
__device__ float g_wqkvT[N_QKV * DIM_];               // w_qkv^T : [n][k]

// ---------------- helpers ----------------
__device__ __forceinline__ uint32_t f2tf32(float f) {
    uint32_t r; asm("cvt.rna.tf32.f32 %0, %1;" : "=r"(r) : "f"(f)); return r;
}

__device__ __forceinline__ void mma_tf32(float* c, const uint32_t* a, const uint32_t* b) {
    asm volatile(
        "mma.sync.aligned.m16n8k8.row.col.f32.tf32.tf32.f32 "
        "{%0,%1,%2,%3}, {%4,%5,%6,%7}, {%8,%9}, {%0,%1,%2,%3};"
        : "+f"(c[0]), "+f"(c[1]), "+f"(c[2]), "+f"(c[3])
        : "r"(a[0]), "r"(a[1]), "r"(a[2]), "r"(a[3]), "r"(b[0]), "r"(b[1]));
}

// ---------------- tf32 mma.sync GEMM ----------------
// C[M,N] = A[M,K] @ Bt[N,K]^T, fp32 in/out, tf32 HMMA, per-batch Bt supported.
// CTA 128x128, k-tile 32, 8 warps (2m x 4n), warp tile 64x32.
#define TM_BM 128
#define TM_BN 128
#define TM_BK 32
#define TM_PAD 36    // smem row stride in floats -> conflict-free fragment gathers

__global__ __launch_bounds__(256) void mgemm_k(
    const float* __restrict__ A, int lda,
    const float* __restrict__ Bt, int ldb, long long b_stride,
    float* __restrict__ C, int ldc,
    int rows_per_batch, int K)
{
    __shared__ uint32_t As[TM_BM * TM_PAD];
    __shared__ uint32_t Bs[TM_BN * TM_PAD];

    const int tid  = threadIdx.x;
    const int lane = tid & 31;
    const int wid  = tid >> 5;
    const int wm   = wid & 1;          // 0..1  (m direction, 64 rows each)
    const int wn   = wid >> 1;         // 0..3  (n direction, 32 cols each)
    const int gid  = lane >> 2;        // groupID 0..7
    const int tig  = lane & 3;         // threadInGroup 0..3

    const int m0 = blockIdx.y * TM_BM;
    const int n0 = blockIdx.x * TM_BN;
    const int batch = m0 / rows_per_batch;
    const float* Ap = A  + (size_t)m0 * lda;
    const float* Bp = Bt + (size_t)batch * b_stride + (size_t)n0 * ldb;

    float acc[4][4][4];
    #pragma unroll
    for (int mt = 0; mt < 4; mt++)
        #pragma unroll
        for (int nt = 0; nt < 4; nt++)
            #pragma unroll
            for (int r = 0; r < 4; r++) acc[mt][nt][r] = 0.f;

    for (int kt = 0; kt < K; kt += TM_BK) {
        // stage A tile (128 x 32) as tf32, row-major with pad
        #pragma unroll
        for (int i = 0; i < 4; i++) {
            int idx = i * 256 + tid;          // 0..1023
            int r = idx >> 3, c4 = idx & 7;
            float4 v = *(const float4*)(Ap + (size_t)r * lda + kt + c4 * 4);
            uint32_t* d = &As[r * TM_PAD + c4 * 4];
            d[0] = f2tf32(v.x); d[1] = f2tf32(v.y);
            d[2] = f2tf32(v.z); d[3] = f2tf32(v.w);
        }
        // stage Bt tile (128 x 32)
        #pragma unroll
        for (int i = 0; i < 4; i++) {
            int idx = i * 256 + tid;
            int r = idx >> 3, c4 = idx & 7;
            float4 v = *(const float4*)(Bp + (size_t)r * ldb + kt + c4 * 4);
            uint32_t* d = &Bs[r * TM_PAD + c4 * 4];
            d[0] = f2tf32(v.x); d[1] = f2tf32(v.y);
            d[2] = f2tf32(v.z); d[3] = f2tf32(v.w);
        }
        __syncthreads();

        #pragma unroll
        for (int ks = 0; ks < TM_BK / 8; ks++) {
            const int kc = ks * 8 + tig;
            uint32_t af[4][4], bf[4][2];
            #pragma unroll
            for (int mt = 0; mt < 4; mt++) {
                int row = wm * 64 + mt * 16 + gid;
                af[mt][0] = As[row * TM_PAD + kc];
                af[mt][1] = As[(row + 8) * TM_PAD + kc];
                af[mt][2] = As[row * TM_PAD + kc + 4];
                af[mt][3] = As[(row + 8) * TM_PAD + kc + 4];
            }
            #pragma unroll
            for (int nt = 0; nt < 4; nt++) {
                int nrow = wn * 32 + nt * 8 + gid;
                bf[nt][0] = Bs[nrow * TM_PAD + kc];
                bf[nt][1] = Bs[nrow * TM_PAD + kc + 4];
            }
            #pragma unroll
            for (int mt = 0; mt < 4; mt++)
                #pragma unroll
                for (int nt = 0; nt < 4; nt++)
                    mma_tf32(acc[mt][nt], af[mt], bf[nt]);
        }
        __syncthreads();
    }

    // epilogue
    #pragma unroll
    for (int mt = 0; mt < 4; mt++) {
        #pragma unroll
        for (int nt = 0; nt < 4; nt++) {
            int row = m0 + wm * 64 + mt * 16 + gid;
            int col = n0 + wn * 32 + nt * 8 + tig * 2;
            *(float2*)(C + (size_t)row * ldc + col) =
                make_float2(acc[mt][nt][0], acc[mt][nt][1]);
            *(float2*)(C + (size_t)(row + 8) * ldc + col) =
                make_float2(acc[mt][nt][2], acc[mt][nt][3]);
        }
    }
}

// ---------------- small transpose: w_qkv [K=256, N=768] -> [N][K] ----------------
__global__ void transp_k(const float* __restrict__ w, float* __restrict__ wT) {
    int idx = blockIdx.x * blockDim.x + threadIdx.x;
    if (idx >= N_QKV * DIM_) return;
    int n = idx / DIM_, k = idx % DIM_;
    wT[idx] = w[(size_t)k * N_QKV + n];
}

// ---------------- depthwise 3x3 conv, SAME, NHWC ----------------
__global__ void dwconv_k(const float* __restrict__ in,
                         const float* __restrict__ w,
                         float* __restrict__ out)
{
    const int C4 = N_QKV / 4;   // 192
    int idx = blockIdx.x * blockDim.x + threadIdx.x;
    if (idx >= B_ * H_ * W_ * C4) return;
    int c4 = idx % C4;
    int t  = idx / C4;
    int xx = t % W_;  t /= W_;
    int yy = t % H_;
    int b  = t / H_;

    float4 acc = make_float4(0.f, 0.f, 0.f, 0.f);
    #pragma unroll
    for (int dy = 0; dy < 3; dy++) {
        int y2 = yy + dy - 1;
        if ((unsigned)y2 >= (unsigned)H_) continue;
        #pragma unroll
        for (int dx = 0; dx < 3; dx++) {
            int x2 = xx + dx - 1;
            if ((unsigned)x2 >= (unsigned)W_) continue;
            float4 iv = *(const float4*)(in + ((size_t)(b*H_ + y2)*W_ + x2)*N_QKV + c4*4);
            float4 wv = *(const float4*)(w  + (size_t)(dy*3 + dx)*N_QKV + c4*4);
            acc.x += iv.x*wv.x; acc.y += iv.y*wv.y;
            acc.z += iv.z*wv.z; acc.w += iv.w*wv.w;
        }
    }
    *(float4*)(out + ((size_t)(b*H_ + yy)*W_ + xx)*N_QKV + c4*4) = acc;
}

// ---------------- attention partials: per (b,head,slice) k^T q over its slice ------
__global__ __launch_bounds__(256) void attn_part_k(
    const float* __restrict__ qkv2,
    const float* __restrict__ mean_q, const float* __restrict__ var_q,
    const float* __restrict__ mean_k, const float* __restrict__ var_k,
    float* __restrict__ part)
{
    const int bh = blockIdx.x;
    const int sl = blockIdx.y;
    const int b = bh >> 4, h = bh & 15;
    __shared__ float qs[64][16];
    __shared__ float ks[64][16];
    __shared__ float red[4][16][16];

    const int tid = threadIdx.x;
    const int g  = tid >> 6;
    const int r  = tid & 63;
    const int i  = r >> 2;
    const int j4 = r & 3;
    const int ls = tid >> 2;
    const int li = (tid & 3) * 4;
    const float* base = qkv2 + (size_t)b * HW_ * N_QKV + h * DH_;

    float acc0 = 0.f, acc1 = 0.f, acc2 = 0.f, acc3 = 0.f;
    const int s_beg = sl * (HW_ / SLICES), s_end = s_beg + HW_ / SLICES;

    for (int s0 = s_beg; s0 < s_end; s0 += 64) {
        int s = s0 + ls;
        float mq = mean_q[s], rvq = rsqrtf(var_q[s]);
        float mk = mean_k[s], rvk = rsqrtf(var_k[s]);
        const float* p = base + (size_t)s * N_QKV + li;
        float4 qv = *(const float4*)(p);
        float4 kv = *(const float4*)(p + DIM_);
        qs[ls][li+0] = (qv.x - mq) * rvq;
        qs[ls][li+1] = (qv.y - mq) * rvq;
        qs[ls][li+2] = (qv.z - mq) * rvq;
        qs[ls][li+3] = (qv.w - mq) * rvq;
        ks[ls][li+0] = (kv.x - mk) * rvk;
        ks[ls][li+1] = (kv.y - mk) * rvk;
        ks[ls][li+2] = (kv.z - mk) * rvk;
        ks[ls][li+3] = (kv.w - mk) * rvk;
        __syncthreads();

        #pragma unroll
        for (int t = 0; t < 16; t++) {
            int ss = g * 16 + t;
            float kval = ks[ss][i];
            acc0 += kval * qs[ss][j4*4+0];
            acc1 += kval * qs[ss][j4*4+1];
            acc2 += kval * qs[ss][j4*4+2];
            acc3 += kval * qs[ss][j4*4+3];
        }
        __syncthreads();
    }

    red[g][i][j4*4+0] = acc0;
    red[g][i][j4*4+1] = acc1;
    red[g][i][j4*4+2] = acc2;
    red[g][i][j4*4+3] = acc3;
    __syncthreads();

    const int i2 = tid >> 4, j2 = tid & 15;
    float a = red[0][i2][j2] + red[1][i2][j2] + red[2][i2][j2] + red[3][i2][j2];
    part[((size_t)(sl * (B_*HEADS_) + bh)) * 256 + i2 * 16 + j2] = a;
}

// ---------------- reduce slices + temperature + softmax(axis=-2) ----------------
__global__ __launch_bounds__(256) void attn_fin_k(
    const float* __restrict__ part, const float* __restrict__ temp,
    float* __restrict__ attn_out)
{
    const int bh = blockIdx.x;
    __shared__ float sm[16][16];
    const int tid = threadIdx.x;
    const int i2 = tid >> 4, j2 = tid & 15;

    float a = 0.f;
    #pragma unroll
    for (int sl = 0; sl < SLICES; sl++)
        a += part[((size_t)(sl * (B_*HEADS_) + bh)) * 256 + tid];
    a *= temp[j2];
    sm[i2][j2] = a;
    __syncthreads();

    if (tid < 16) {
        int j = tid;
        float mx = -1e30f;
        #pragma unroll
        for (int ii = 0; ii < 16; ii++) mx = fmaxf(mx, sm[ii][j]);
        float e[16]; float ssum = 0.f;
        #pragma unroll
        for (int ii = 0; ii < 16; ii++) { e[ii] = expf(sm[ii][j] - mx); ssum += e[ii]; }
        float inv = 1.f / ssum;
        #pragma unroll
        for (int ii = 0; ii < 16; ii++)
            attn_out[((size_t)bh * 16 + ii) * 16 + j] = e[ii] * inv;
    }
}

// ---------------- WfT[b][e][h*16+d] = sum_j attn[b,h,d,j] * w_out[h*16+j][e] --------
__global__ __launch_bounds__(256) void wfused_k(const float* __restrict__ attn,
                                                const float* __restrict__ w_out,
                                                float* __restrict__ wfT)
{
    const int bh = blockIdx.x;
    const int b = bh >> 4, h = bh & 15;
    const int e = threadIdx.x;
    __shared__ float a[16][16];
    a[threadIdx.x >> 4][threadIdx.x & 15] = attn[(size_t)bh * 256 + threadIdx.x];
    __syncthreads();

    float w[16];
    #pragma unroll
    for (int j = 0; j < 16; j++) w[j] = w_out[(size_t)(h*16 + j) * DIM_ + e];
    #pragma unroll
    for (int d = 0; d < 16; d++) {
        float s = 0.f;
        #pragma unroll
        for (int j = 0; j < 16; j++) s += a[d][j] * w[j];
        wfT[((size_t)b * DIM_ + e) * DIM_ + (h*16 + d)] = s;
    }
}

// ---------------- launch ----------------
extern "C" void kernel_launch(void* const* d_in, const int* in_sizes, int n_in,
                              void* d_out, int out_size)
{
    const float* x      = (const float*)d_in[0];
    const float* w_qkv  = (const float*)d_in[1];
    const float* w_dw   = (const float*)d_in[2];
    const float* w_out  = (const float*)d_in[3];
    const float* temp   = (const float*)d_in[4];
    const float* mean_q = (const float*)d_in[5];
    const float* var_q  = (const float*)d_in[6];
    const float* mean_k = (const float*)d_in[7];
    const float* var_k  = (const float*)d_in[8];
    float* out = (float*)d_out;

    float *qkv, *qkv2, *part, *attn, *wfT, *wqkvT;
    cudaGetSymbolAddress((void**)&qkv,   g_qkv);
    cudaGetSymbolAddress((void**)&qkv2,  g_qkv2);
    cudaGetSymbolAddress((void**)&part,  g_part);
    cudaGetSymbolAddress((void**)&attn,  g_attn);
    cudaGetSymbolAddress((void**)&wfT,   g_wfT);
    cudaGetSymbolAddress((void**)&wqkvT, g_wqkvT);

    // 0) transpose w_qkv -> [N][K]
    transp_k<<<(N_QKV * DIM_ + 255) / 256, 256>>>(w_qkv, wqkvT);

    // 1) QKV projection: (131072 x 256) @ (256 x 768) via tf32 mma.sync
    mgemm_k<<<dim3(N_QKV / TM_BN, M_TOTAL / TM_BM), 256>>>(
        x, DIM_, wqkvT, DIM_, 0, qkv, N_QKV, M_TOTAL, DIM_);

    // 2) depthwise 3x3 conv, SAME
    {
        int total = B_ * H_ * W_ * (N_QKV / 4);
        dwconv_k<<<(total + 255) / 256, 256>>>(qkv, w_dw, qkv2);
    }

    // 3) channel attention partials (8 spatial slices) + reduce/softmax
    attn_part_k<<<dim3(B_ * HEADS_, SLICES), 256>>>(qkv2, mean_q, var_q, mean_k, var_k, part);
    attn_fin_k<<<B_ * HEADS_, 256>>>(part, temp, attn);

    // 4) fold attn into output projection (transposed for mma B operand)
    wfused_k<<<B_ * HEADS_, 256>>>(attn, w_out, wfT);

    // 5) out = v_flat @ WfT[b]^T : (16384 x 256) @ (256 x 256) x 8 batches
    mgemm_k<<<dim3(DIM_ / TM_BN, M_TOTAL / TM_BM), 256>>>(
        qkv2 + 2 * DIM_, N_QKV, wfT, DIM_, (long long)DIM_ * DIM_, out, DIM_, HW_, DIM_);
}